// round 10
// baseline (speedup 1.0000x reference)
#include <cuda_runtime.h>
#include <cuda_fp16.h>
#include <math.h>
#include <cfloat>
#include <cstdint>

#define B_   128
#define N_   8732
#define C_   512
#define H_   19
#define FG_  19
#define HID_ 4096

// ---------------------------------------------------------------------------
// scratch (device globals — no allocation allowed)
// ---------------------------------------------------------------------------
__device__ __align__(16) __half g_featH[B_*C_];
__device__ __align__(16) __half g_h1h[B_*HID_];
__device__ float g_h2[B_*HID_];
__device__ int   g_bins[B_*4];
__device__ int   g_valid[B_];
__device__ float g_part[4*B_*HID_];                 // split-K partials (S<=4)
__device__ float g_w3t[FG_*HID_];                   // w3 transposed
__device__ __align__(16) __half g_w1h[C_*HID_];     // 4 MB
__device__ __align__(16) __half g_w2h[HID_*HID_];   // 32 MB

// ---------------------------------------------------------------------------
// helpers
// ---------------------------------------------------------------------------
#define MMA_F16(c, a, b0, b1)                                               \
    asm volatile("mma.sync.aligned.m16n8k16.row.col.f32.f16.f16.f32 "       \
        "{%0,%1,%2,%3}, {%4,%5,%6,%7}, {%8,%9}, {%0,%1,%2,%3};"             \
        : "+f"((c)[0]), "+f"((c)[1]), "+f"((c)[2]), "+f"((c)[3])            \
        : "r"((a)[0]), "r"((a)[1]), "r"((a)[2]), "r"((a)[3]),               \
          "r"(b0), "r"(b1))

#define LDSM_X4(r, addr)                                                    \
    asm volatile("ldmatrix.sync.aligned.m8n8.x4.shared.b16 "                \
        "{%0,%1,%2,%3}, [%4];"                                              \
        : "=r"((r)[0]), "=r"((r)[1]), "=r"((r)[2]), "=r"((r)[3])            \
        : "r"(addr) : "memory")

#define LDSM_X4T(r, addr)                                                   \
    asm volatile("ldmatrix.sync.aligned.m8n8.x4.trans.shared.b16 "          \
        "{%0,%1,%2,%3}, [%4];"                                              \
        : "=r"((r)[0]), "=r"((r)[1]), "=r"((r)[2]), "=r"((r)[3])            \
        : "r"(addr) : "memory")

#define CP_ASYNC16(dst, src)                                                \
    asm volatile("cp.async.cg.shared.global [%0], [%1], 16;"                \
        :: "r"(dst), "l"(src) : "memory")
#define CP_COMMIT()  asm volatile("cp.async.commit_group;" ::: "memory")
#define CP_WAIT(n)   asm volatile("cp.async.wait_group %0;" :: "n"(n) : "memory")

// ---------------------------------------------------------------------------
// Kernel 0: f32 -> f16 bulk convert (8 elems / thread)
// ---------------------------------------------------------------------------
__global__ void cvt_f16_kernel(const float* __restrict__ in,
                               __half* __restrict__ out, int n8)
{
    int i = blockIdx.x * 256 + threadIdx.x;
    if (i >= n8) return;
    const float4* p = (const float4*)in + (size_t)i * 2;
    float4 v0 = p[0], v1 = p[1];
    __half2 h0 = __floats2half2_rn(v0.x, v0.y);
    __half2 h1 = __floats2half2_rn(v0.z, v0.w);
    __half2 h2 = __floats2half2_rn(v1.x, v1.y);
    __half2 h3 = __floats2half2_rn(v1.z, v1.w);
    uint4 o;
    o.x = *(uint32_t*)&h0; o.y = *(uint32_t*)&h1;
    o.z = *(uint32_t*)&h2; o.w = *(uint32_t*)&h3;
    ((uint4*)out)[i] = o;
}

// ---------------------------------------------------------------------------
// Kernel 1: per-batch best car prior -> decode -> clip -> boxes/valid + bins
// ---------------------------------------------------------------------------
__global__ void best_prior_kernel(const float* __restrict__ loc,
                                  const float* __restrict__ conf,
                                  const float* __restrict__ priors,
                                  float* __restrict__ out)
{
    int b = blockIdx.x, tid = threadIdx.x;
    const float2* cb = (const float2*)(conf + (size_t)b * N_ * 2);

    float best = -FLT_MAX;
    int   bidx = 0x7fffffff;
    int   anyc = 0;

    for (int i = tid; i < N_; i += 256) {
        float2 c = cb[i];
        if (c.y > c.x) {
            anyc = 1;
            float p1 = 1.0f / (1.0f + expf(c.x - c.y));
            if (p1 > best || (p1 == best && i < bidx)) { best = p1; bidx = i; }
        }
    }

    int has = __syncthreads_or(anyc);

    __shared__ float sv[256];
    __shared__ int   si[256];
    sv[tid] = best; si[tid] = bidx;
    __syncthreads();
    for (int s = 128; s > 0; s >>= 1) {
        if (tid < s) {
            float v2 = sv[tid+s]; int i2 = si[tid+s];
            if (v2 > sv[tid] || (v2 == sv[tid] && i2 < si[tid])) { sv[tid]=v2; si[tid]=i2; }
        }
        __syncthreads();
    }

    if (tid == 0) {
        float bx0=0.f,bx1=0.f,bx2=0.f,bx3=0.f;
        int v = 0;
        int n0=0,n1=0,n2=0,n3=0;
        if (has) {
            int idx = si[0];
            float p0 = priors[4*idx+0], p1p = priors[4*idx+1];
            float p2 = priors[4*idx+2], p3  = priors[4*idx+3];
            const float* l = loc + ((size_t)b * N_ + idx) * 4;
            float cx = p0 + l[0] * 0.1f * p2;
            float cy = p1p + l[1] * 0.1f * p3;
            float w  = p2 * expf(l[2] * 0.2f);
            float h  = p3 * expf(l[3] * 0.2f);
            float x1 = cx - 0.5f*w, y1 = cy - 0.5f*h;
            float x2 = x1 + w,      y2 = y1 + h;
            v = (x2 > x1) && (y2 > y1);
            bx0 = fminf(fmaxf(x1, 0.f), 1.f);
            bx1 = fminf(fmaxf(y1, 0.f), 1.f);
            bx2 = fminf(fmaxf(x2, 0.f), 1.f);
            bx3 = fminf(fmaxf(y2, 0.f), 1.f);
            const float step = (float)(300.0 / 19.0);
            float t;
            t = fminf(fmaxf(bx0*300.0f,0.f),300.f)/step; n0 = (int)floorf(fminf(fmaxf(t,0.f),18.f));
            t = fminf(fmaxf(bx1*300.0f,0.f),300.f)/step; n1 = (int)floorf(fminf(fmaxf(t,0.f),18.f));
            t = fminf(fmaxf(bx2*300.0f,0.f),300.f)/step; n2 = (int)floorf(fminf(fmaxf(t,0.f),18.f));
            t = fminf(fmaxf(bx3*300.0f,0.f),300.f)/step; n3 = (int)floorf(fminf(fmaxf(t,0.f),18.f));
        }
        out[2432 + b*4 + 0] = bx0;
        out[2432 + b*4 + 1] = bx1;
        out[2432 + b*4 + 2] = bx2;
        out[2432 + b*4 + 3] = bx3;
        out[2944 + b] = v ? 1.0f : 0.0f;
        g_valid[b]   = v;
        g_bins[b*4+0] = n0; g_bins[b*4+1] = n1;
        g_bins[b*4+2] = n2; g_bins[b*4+3] = n3;
    }
}

// ---------------------------------------------------------------------------
// Kernel 2: masked global max pool -> g_featH [B, C] f16 (coalesced scan)
// ---------------------------------------------------------------------------
__global__ void extract_kernel(const float* __restrict__ feats)
{
    int b    = blockIdx.x;
    int warp = threadIdx.x >> 5;
    int lane = threadIdx.x & 31;
    int c    = blockIdx.y * 8 + warp;

    if (!g_valid[b]) { if (lane == 0) g_featH[b*C_ + c] = __float2half(0.f); return; }

    int x1 = g_bins[b*4+0], y1 = g_bins[b*4+1];
    int x2 = g_bins[b*4+2], y2 = g_bins[b*4+3];

    const float* f = feats + ((size_t)(b * C_ + c)) * (H_ * H_);
    float m = -FLT_MAX;
    for (int t = lane; t < H_ * H_; t += 32) {
        float v = f[t];
        int y = t / H_;
        int x = t - y * H_;
        bool in = (y >= y1) & (y <= y2) & (x >= x1) & (x <= x2);
        m = fmaxf(m, in ? v : -FLT_MAX);
    }
    #pragma unroll
    for (int o = 16; o; o >>= 1) m = fmaxf(m, __shfl_xor_sync(0xffffffffu, m, o));
    if (lane == 0) g_featH[b*C_ + c] = __float2half_rn(m);
}

// ---------------------------------------------------------------------------
// Kernel 3: f16 mma GEMM, cp.async 3-stage pipeline, split-K.
//   part[split][128][HID_] = A[128, Ktot] @ Bw[Ktot, HID_]  (both f16, f32 acc)
//   BM=128, BN=64, BK=64; 8 warps, warp tile 32x32.
//   SMEM rows padded to 144 B (conflict-free for ldmatrix).
// ---------------------------------------------------------------------------
#define PITCH      144
#define A_BYTES    (128*PITCH)              // 18432
#define B_BYTES    (64*PITCH)               //  9216
#define STG_BYTES  (A_BYTES + B_BYTES)      // 27648
#define NSTAGE     3
#define GEMM_SMEM  (NSTAGE*STG_BYTES)       // 82944

__global__ __launch_bounds__(256, 2)
void gemm_f16_kernel(int Ktot, int KSPLIT,
                     const __half* __restrict__ Aw, const __half* __restrict__ Bw,
                     float* __restrict__ part)
{
    extern __shared__ uint8_t smraw[];

    const int tid  = threadIdx.x;
    const int wid  = tid >> 5;
    const int lane = tid & 31;
    const int gid  = lane >> 2;
    const int tig  = lane & 3;
    const int n0   = blockIdx.x * 64;
    const int ks   = blockIdx.y * KSPLIT;
    const int NCH  = KSPLIT >> 6;           // BK=64 chunks
    const int mbase = (wid & 3) * 32;
    const int nbase = (wid >> 2) * 32;

    const uint32_t sbase = (uint32_t)__cvta_generic_to_shared(smraw);

    const int l15  = lane & 15;
    const int lhi8 = (lane >> 4) * 8;
    const uint32_t a_off = (uint32_t)((mbase + l15) * PITCH + lhi8 * 2);
    const uint32_t b_off = (uint32_t)(l15 * PITCH + (nbase + lhi8) * 2);

    float acc[2][4][4];
    #pragma unroll
    for (int i = 0; i < 2; i++)
        #pragma unroll
        for (int j = 0; j < 4; j++)
            #pragma unroll
            for (int q = 0; q < 4; q++) acc[i][j][q] = 0.f;

    // issue one BK=64 chunk into stage buffer: A 1024x16B + B 512x16B
    #define ISSUE(stage, k0) do {                                           \
        uint32_t dA = sbase + (uint32_t)((stage) * STG_BYTES);              \
        _Pragma("unroll")                                                   \
        for (int j = 0; j < 4; j++) {                                       \
            int idx = tid + j * 256;                                        \
            int row = idx >> 3, q = idx & 7;                                \
            const __half* src = Aw + (size_t)row * Ktot + (k0) + q * 8;     \
            CP_ASYNC16(dA + (uint32_t)(row * PITCH + q * 16), src);         \
        }                                                                   \
        uint32_t dB = dA + A_BYTES;                                         \
        _Pragma("unroll")                                                   \
        for (int j = 0; j < 2; j++) {                                       \
            int idx = tid + j * 256;                                        \
            int kr = idx >> 3, q = idx & 7;                                 \
            const __half* src = Bw + (size_t)((k0) + kr) * HID_ + n0 + q*8; \
            CP_ASYNC16(dB + (uint32_t)(kr * PITCH + q * 16), src);          \
        }                                                                   \
    } while (0)

    // prologue: stages 0..NSTAGE-2
    #pragma unroll
    for (int st = 0; st < NSTAGE - 1; st++) {
        if (st < NCH) ISSUE(st, ks + st * 64);
        CP_COMMIT();
    }

    for (int c = 0; c < NCH; c++) {
        CP_WAIT(NSTAGE - 2);
        __syncthreads();

        // issue chunk c+NSTAGE-1 into buffer (c+NSTAGE-1)%NSTAGE
        // (that buffer was computed at iter c-1; the sync above makes it safe)
        int nc = c + NSTAGE - 1;
        if (nc < NCH) ISSUE(nc % NSTAGE, ks + nc * 64);
        CP_COMMIT();

        const int stg = c % NSTAGE;
        const uint32_t AhA = sbase + (uint32_t)(stg * STG_BYTES) + a_off;
        const uint32_t BhA = sbase + (uint32_t)(stg * STG_BYTES + A_BYTES) + b_off;

        #pragma unroll
        for (int s = 0; s < 4; s++) {
            uint32_t a[2][4], bh[2][4];
            LDSM_X4(a[0], AhA + s * 32);
            LDSM_X4(a[1], AhA + s * 32 + 16 * PITCH);
            LDSM_X4T(bh[0], BhA + s * (16 * PITCH));
            LDSM_X4T(bh[1], BhA + s * (16 * PITCH) + 32);

            #pragma unroll
            for (int mt = 0; mt < 2; mt++) {
                #pragma unroll
                for (int ntp = 0; ntp < 2; ntp++) {
                    MMA_F16(acc[mt][2*ntp+0], a[mt], bh[ntp][0], bh[ntp][1]);
                    MMA_F16(acc[mt][2*ntp+1], a[mt], bh[ntp][2], bh[ntp][3]);
                }
            }
        }
    }

    // epilogue: partial sums
    #pragma unroll
    for (int mt = 0; mt < 2; mt++) {
        int row = mbase + mt * 16 + gid;
        float* base = part + ((size_t)blockIdx.y * 128 + row) * HID_ + n0 + nbase;
        #pragma unroll
        for (int nt = 0; nt < 4; nt++) {
            float* d = base + nt * 8 + tig * 2;
            *(float2*)d               = make_float2(acc[mt][nt][0], acc[mt][nt][1]);
            *(float2*)(d + 8 * HID_)  = make_float2(acc[mt][nt][2], acc[mt][nt][3]);
        }
    }
    #undef ISSUE
}

// ---------------------------------------------------------------------------
// Kernel 4a: split-K reduce + bias + relu -> f16 out (feeds next GEMM)
// ---------------------------------------------------------------------------
__global__ void reduce_bias_h_kernel(int S, const float* __restrict__ part,
                                     const float* __restrict__ bias,
                                     __half* __restrict__ out)
{
    int i4 = blockIdx.x * 256 + threadIdx.x;
    const int MN = B_ * HID_;
    int base = i4 * 4;
    if (base >= MN) return;
    float4 s = make_float4(0.f, 0.f, 0.f, 0.f);
    for (int p = 0; p < S; p++) {
        float4 v = *(const float4*)(part + (size_t)p * MN + base);
        s.x += v.x; s.y += v.y; s.z += v.z; s.w += v.w;
    }
    int n = base & (HID_ - 1);
    s.x = fmaxf(s.x + bias[n + 0], 0.f);
    s.y = fmaxf(s.y + bias[n + 1], 0.f);
    s.z = fmaxf(s.z + bias[n + 2], 0.f);
    s.w = fmaxf(s.w + bias[n + 3], 0.f);
    __half2 h0 = __floats2half2_rn(s.x, s.y);
    __half2 h1 = __floats2half2_rn(s.z, s.w);
    uint2 o;
    o.x = *(uint32_t*)&h0; o.y = *(uint32_t*)&h1;
    *(uint2*)(out + base) = o;
}

// ---------------------------------------------------------------------------
// Kernel 4b: split-K reduce + bias + relu -> f32 out (feeds fc3)
// ---------------------------------------------------------------------------
__global__ void reduce_bias_f_kernel(int S, const float* __restrict__ part,
                                     const float* __restrict__ bias,
                                     float* __restrict__ out)
{
    int i4 = blockIdx.x * 256 + threadIdx.x;
    const int MN = B_ * HID_;
    int base = i4 * 4;
    if (base >= MN) return;
    float4 s = make_float4(0.f, 0.f, 0.f, 0.f);
    for (int p = 0; p < S; p++) {
        float4 v = *(const float4*)(part + (size_t)p * MN + base);
        s.x += v.x; s.y += v.y; s.z += v.z; s.w += v.w;
    }
    int n = base & (HID_ - 1);
    s.x = fmaxf(s.x + bias[n + 0], 0.f);
    s.y = fmaxf(s.y + bias[n + 1], 0.f);
    s.z = fmaxf(s.z + bias[n + 2], 0.f);
    s.w = fmaxf(s.w + bias[n + 3], 0.f);
    *(float4*)(out + base) = s;
}

// ---------------------------------------------------------------------------
// Kernel 5a: transpose w3 [4096,19] -> w3t [19,4096]
// ---------------------------------------------------------------------------
__global__ void w3t_kernel(const float* __restrict__ w3, float* __restrict__ w3t)
{
    int k = blockIdx.x * 256 + threadIdx.x;
    if (k >= HID_) return;
    #pragma unroll
    for (int c = 0; c < FG_; c++)
        w3t[c * HID_ + k] = w3[k * FG_ + c];
}

// ---------------------------------------------------------------------------
// Kernel 5b: final FC  out[b,col] = dot(h2[b], w3t[col]) + b3[col]
// ---------------------------------------------------------------------------
__global__ void fc3_kernel(const float* __restrict__ A, const float* __restrict__ Wt,
                           const float* __restrict__ bias, float* __restrict__ out)
{
    int gw   = blockIdx.x * 8 + (threadIdx.x >> 5);
    int lane = threadIdx.x & 31;
    if (gw >= B_ * FG_) return;
    int b = gw / FG_, col = gw - b * FG_;

    const float4* a = (const float4*)(A  + (size_t)b   * HID_);
    const float4* w = (const float4*)(Wt + (size_t)col * HID_);
    float s = 0.f;
    #pragma unroll 4
    for (int i = lane; i < HID_/4; i += 32) {
        float4 av = a[i], wv = w[i];
        s += av.x*wv.x + av.y*wv.y + av.z*wv.z + av.w*wv.w;
    }
    #pragma unroll
    for (int o = 16; o; o >>= 1) s += __shfl_xor_sync(0xffffffffu, s, o);
    if (lane == 0) out[b * FG_ + col] = s + bias[col];
}

// ---------------------------------------------------------------------------
extern "C" void kernel_launch(void* const* d_in, const int* in_sizes, int n_in,
                              void* d_out, int out_size)
{
    const float* loc      = (const float*)d_in[0];
    const float* conf     = (const float*)d_in[1];
    const float* priors   = (const float*)d_in[2];
    const float* features = (const float*)d_in[3];
    const float* w1 = (const float*)d_in[4];
    const float* b1 = (const float*)d_in[5];
    const float* w2 = (const float*)d_in[6];
    const float* b2 = (const float*)d_in[7];
    const float* w3 = (const float*)d_in[8];
    const float* b3 = (const float*)d_in[9];
    float* out = (float*)d_out;

    void *pfH, *p1h, *p2, *ppart, *pw3t, *pw1h, *pw2h;
    cudaGetSymbolAddress(&pfH,   g_featH);
    cudaGetSymbolAddress(&p1h,   g_h1h);
    cudaGetSymbolAddress(&p2,    g_h2);
    cudaGetSymbolAddress(&ppart, g_part);
    cudaGetSymbolAddress(&pw3t,  g_w3t);
    cudaGetSymbolAddress(&pw1h,  g_w1h);
    cudaGetSymbolAddress(&pw2h,  g_w2h);

    cudaFuncSetAttribute(gemm_f16_kernel,
                         cudaFuncAttributeMaxDynamicSharedMemorySize, GEMM_SMEM);

    // weight conversions (per launch, deterministic)
    cvt_f16_kernel<<<(HID_*HID_/8 + 255)/256, 256>>>(w2, (__half*)pw2h, HID_*HID_/8);
    cvt_f16_kernel<<<(C_*HID_/8 + 255)/256, 256>>>(w1, (__half*)pw1h, C_*HID_/8);

    best_prior_kernel<<<B_, 256>>>(loc, conf, priors, out);
    extract_kernel<<<dim3(B_, C_/8), 256>>>(features);
    w3t_kernel<<<HID_/256, 256>>>(w3, (float*)pw3t);

    // GEMM1: [128,512] @ [512,4096], split-K=4 (KSPLIT=128, NCH=2)
    gemm_f16_kernel<<<dim3(HID_/64, 4), 256, GEMM_SMEM>>>(C_, 128,
        (const __half*)pfH, (const __half*)pw1h, (float*)ppart);
    reduce_bias_h_kernel<<<(B_*HID_/4 + 255)/256, 256>>>(4,
        (const float*)ppart, b1, (__half*)p1h);

    // GEMM2: [128,4096] @ [4096,4096], split-K=4 (KSPLIT=1024, NCH=16)
    gemm_f16_kernel<<<dim3(HID_/64, 4), 256, GEMM_SMEM>>>(HID_, 1024,
        (const __half*)p1h, (const __half*)pw2h, (float*)ppart);
    reduce_bias_f_kernel<<<(B_*HID_/4 + 255)/256, 256>>>(4,
        (const float*)ppart, b2, (float*)p2);

    fc3_kernel<<<(B_*FG_ + 7)/8, 256>>>((const float*)p2, (const float*)pw3t, b3, out);
}

// round 11
// speedup vs baseline: 1.3411x; 1.3411x over previous
#include <cuda_runtime.h>
#include <cuda_fp16.h>
#include <math.h>
#include <cfloat>
#include <cstdint>

#define B_   128
#define N_   8732
#define C_   512
#define H_   19
#define FG_  19
#define HID_ 4096

// ---------------------------------------------------------------------------
// scratch (device globals — no allocation allowed)
// ---------------------------------------------------------------------------
__device__ __align__(16) __half g_featH[B_*C_];
__device__ __align__(16) __half g_h1h[B_*HID_];
__device__ float g_h2[B_*HID_];
__device__ int   g_bins[B_*4];
__device__ int   g_valid[B_];
__device__ float g_part[4*B_*HID_];     // split-K partials (S<=4)
__device__ float g_w3t[FG_*HID_];       // w3 transposed

// ---------------------------------------------------------------------------
// helpers
// ---------------------------------------------------------------------------
#define MMA_F16(c, a, b0, b1)                                               \
    asm volatile("mma.sync.aligned.m16n8k16.row.col.f32.f16.f16.f32 "       \
        "{%0,%1,%2,%3}, {%4,%5,%6,%7}, {%8,%9}, {%0,%1,%2,%3};"             \
        : "+f"((c)[0]), "+f"((c)[1]), "+f"((c)[2]), "+f"((c)[3])            \
        : "r"((a)[0]), "r"((a)[1]), "r"((a)[2]), "r"((a)[3]),               \
          "r"(b0), "r"(b1))

#define LDSM_X4(r, addr)                                                    \
    asm volatile("ldmatrix.sync.aligned.m8n8.x4.shared.b16 "                \
        "{%0,%1,%2,%3}, [%4];"                                              \
        : "=r"((r)[0]), "=r"((r)[1]), "=r"((r)[2]), "=r"((r)[3])            \
        : "r"(addr) : "memory")

#define LDSM_X4T(r, addr)                                                   \
    asm volatile("ldmatrix.sync.aligned.m8n8.x4.trans.shared.b16 "          \
        "{%0,%1,%2,%3}, [%4];"                                              \
        : "=r"((r)[0]), "=r"((r)[1]), "=r"((r)[2]), "=r"((r)[3])            \
        : "r"(addr) : "memory")

#define CP_ASYNC16(dst, src)                                                \
    asm volatile("cp.async.cg.shared.global [%0], [%1], 16;"                \
        :: "r"(dst), "l"(src) : "memory")
#define CP_COMMIT()  asm volatile("cp.async.commit_group;" ::: "memory")
#define CP_WAIT1()   asm volatile("cp.async.wait_group 1;" ::: "memory")

__device__ __forceinline__ uint32_t pack2_f16(float x0, float x1)
{
    __half2 h = __floats2half2_rn(x0, x1);
    return *(uint32_t*)&h;
}

// ---------------------------------------------------------------------------
// Kernel 1: per-batch best car prior -> decode -> clip -> boxes/valid + bins
// ---------------------------------------------------------------------------
__global__ void best_prior_kernel(const float* __restrict__ loc,
                                  const float* __restrict__ conf,
                                  const float* __restrict__ priors,
                                  float* __restrict__ out)
{
    int b = blockIdx.x, tid = threadIdx.x;
    const float2* cb = (const float2*)(conf + (size_t)b * N_ * 2);

    float best = -FLT_MAX;
    int   bidx = 0x7fffffff;
    int   anyc = 0;

    for (int i = tid; i < N_; i += 256) {
        float2 c = cb[i];
        if (c.y > c.x) {
            anyc = 1;
            float p1 = 1.0f / (1.0f + expf(c.x - c.y));
            if (p1 > best || (p1 == best && i < bidx)) { best = p1; bidx = i; }
        }
    }

    int has = __syncthreads_or(anyc);

    __shared__ float sv[256];
    __shared__ int   si[256];
    sv[tid] = best; si[tid] = bidx;
    __syncthreads();
    for (int s = 128; s > 0; s >>= 1) {
        if (tid < s) {
            float v2 = sv[tid+s]; int i2 = si[tid+s];
            if (v2 > sv[tid] || (v2 == sv[tid] && i2 < si[tid])) { sv[tid]=v2; si[tid]=i2; }
        }
        __syncthreads();
    }

    if (tid == 0) {
        float bx0=0.f,bx1=0.f,bx2=0.f,bx3=0.f;
        int v = 0;
        int n0=0,n1=0,n2=0,n3=0;
        if (has) {
            int idx = si[0];
            float p0 = priors[4*idx+0], p1p = priors[4*idx+1];
            float p2 = priors[4*idx+2], p3  = priors[4*idx+3];
            const float* l = loc + ((size_t)b * N_ + idx) * 4;
            float cx = p0 + l[0] * 0.1f * p2;
            float cy = p1p + l[1] * 0.1f * p3;
            float w  = p2 * expf(l[2] * 0.2f);
            float h  = p3 * expf(l[3] * 0.2f);
            float x1 = cx - 0.5f*w, y1 = cy - 0.5f*h;
            float x2 = x1 + w,      y2 = y1 + h;
            v = (x2 > x1) && (y2 > y1);
            bx0 = fminf(fmaxf(x1, 0.f), 1.f);
            bx1 = fminf(fmaxf(y1, 0.f), 1.f);
            bx2 = fminf(fmaxf(x2, 0.f), 1.f);
            bx3 = fminf(fmaxf(y2, 0.f), 1.f);
            const float step = (float)(300.0 / 19.0);
            float t;
            t = fminf(fmaxf(bx0*300.0f,0.f),300.f)/step; n0 = (int)floorf(fminf(fmaxf(t,0.f),18.f));
            t = fminf(fmaxf(bx1*300.0f,0.f),300.f)/step; n1 = (int)floorf(fminf(fmaxf(t,0.f),18.f));
            t = fminf(fmaxf(bx2*300.0f,0.f),300.f)/step; n2 = (int)floorf(fminf(fmaxf(t,0.f),18.f));
            t = fminf(fmaxf(bx3*300.0f,0.f),300.f)/step; n3 = (int)floorf(fminf(fmaxf(t,0.f),18.f));
        }
        out[2432 + b*4 + 0] = bx0;
        out[2432 + b*4 + 1] = bx1;
        out[2432 + b*4 + 2] = bx2;
        out[2432 + b*4 + 3] = bx3;
        out[2944 + b] = v ? 1.0f : 0.0f;
        g_valid[b]   = v;
        g_bins[b*4+0] = n0; g_bins[b*4+1] = n1;
        g_bins[b*4+2] = n2; g_bins[b*4+3] = n3;
    }
}

// ---------------------------------------------------------------------------
// Kernel 2: masked global max pool -> g_featH [B, C] f16
// ALL loads batched first (MLP=12) then masked fmax — kills the latency chain
// ---------------------------------------------------------------------------
__global__ void extract_kernel(const float* __restrict__ feats)
{
    int b    = blockIdx.x;
    int warp = threadIdx.x >> 5;
    int lane = threadIdx.x & 31;
    int c    = blockIdx.y * 8 + warp;

    if (!g_valid[b]) { if (lane == 0) g_featH[b*C_ + c] = __float2half(0.f); return; }

    int x1 = g_bins[b*4+0], y1 = g_bins[b*4+1];
    int x2 = g_bins[b*4+2], y2 = g_bins[b*4+3];

    const float* f = feats + ((size_t)(b * C_ + c)) * (H_ * H_);

    float v[11];
    #pragma unroll
    for (int i = 0; i < 11; i++) v[i] = f[lane + 32 * i];
    float vt = (lane < 9) ? f[352 + lane] : -FLT_MAX;

    float m = -FLT_MAX;
    #pragma unroll
    for (int i = 0; i < 11; i++) {
        int t = lane + 32 * i;
        int y = t / H_;
        int x = t - y * H_;
        bool in = (y >= y1) & (y <= y2) & (x >= x1) & (x <= x2);
        m = fmaxf(m, in ? v[i] : -FLT_MAX);
    }
    {
        int t = 352 + lane;
        int y = t / H_;
        int x = t - y * H_;
        bool in = (lane < 9) & (y >= y1) & (y <= y2) & (x >= x1) & (x <= x2);
        m = fmaxf(m, in ? vt : -FLT_MAX);
    }
    #pragma unroll
    for (int o = 16; o; o >>= 1) m = fmaxf(m, __shfl_xor_sync(0xffffffffu, m, o));
    if (lane == 0) g_featH[b*C_ + c] = __float2half_rn(m);
}

// ---------------------------------------------------------------------------
// Kernel 3: hybrid GEMM — A f16 via cp.async, B f32 fused-convert in stager.
//   part[split][128][HID_] = A[128, Ktot](f16) @ Bw[Ktot, HID_](f32)
//   BM=128, BN=64, BK=32; 8 warps, warp tile 32x32; double-buffered.
// ---------------------------------------------------------------------------
#define A_PITCH   80               // bytes per A row (64 data + 16 pad)
#define B_PITCH   144              // bytes per B k-row (128 data + 16 pad)
#define A_BYTES   (128*A_PITCH)    // 10240
#define B_BYTES   (32*B_PITCH)     //  4608
#define BUF_BYTES (A_BYTES + B_BYTES)   // 14848
#define BUF_U32   (BUF_BYTES/4)
#define A_U32     (A_BYTES/4)

__global__ __launch_bounds__(256, 2)
void gemm_hyb_kernel(int Ktot, int KSPLIT,
                     const __half* __restrict__ Aw, const float* __restrict__ Bw,
                     float* __restrict__ part)
{
    extern __shared__ uint32_t sm[];

    const int tid  = threadIdx.x;
    const int wid  = tid >> 5;
    const int lane = tid & 31;
    const int gid  = lane >> 2;
    const int tig  = lane & 3;
    const int n0   = blockIdx.x * 64;
    const int ks   = blockIdx.y * KSPLIT;
    const int NCH  = KSPLIT >> 5;
    const int mbase = (wid & 3) * 32;
    const int nbase = (wid >> 2) * 32;

    // B staging: thread owns (p, nq): k rows 2p,2p+1, col quad nq*4..+3
    const int bp_p  = tid >> 4;      // 0..15
    const int bp_nq = tid & 15;      // 0..15

    const uint32_t sbase = (uint32_t)__cvta_generic_to_shared(sm);

    const int l15  = lane & 15;
    const int lhi8 = (lane >> 4) * 8;
    const uint32_t a_off = (uint32_t)((mbase + l15) * A_PITCH + lhi8 * 2);
    const uint32_t b_off = (uint32_t)(l15 * B_PITCH + (nbase + lhi8) * 2);

    float acc[2][4][4];
    #pragma unroll
    for (int i = 0; i < 2; i++)
        #pragma unroll
        for (int j = 0; j < 4; j++)
            #pragma unroll
            for (int q = 0; q < 4; q++) acc[i][j][q] = 0.f;

    float4 rb0, rb1;

    // A chunk (128x32 f16 = 8192B = 512x16B): 2 cp.async per thread
    #define ISSUE_A(buf, k0) do {                                           \
        uint32_t dA = sbase + (uint32_t)((buf) * BUF_BYTES);                \
        _Pragma("unroll")                                                   \
        for (int j = 0; j < 2; j++) {                                       \
            int idx = tid + j * 256;                                        \
            int row = idx >> 2, q = idx & 3;                                \
            const __half* src = Aw + (size_t)row * Ktot + (k0) + q * 8;     \
            CP_ASYNC16(dA + (uint32_t)(row * A_PITCH + q * 16), src);       \
        }                                                                   \
    } while (0)

    #define LOAD_B(k0) do {                                                 \
        const float* bp = Bw + (size_t)((k0) + 2 * bp_p) * HID_             \
                          + n0 + bp_nq * 4;                                 \
        rb0 = *(const float4*)bp;                                           \
        rb1 = *(const float4*)(bp + HID_);                                  \
    } while (0)

    #define STORE_B(buf) do {                                               \
        uint32_t* Bh = sm + (buf) * BUF_U32 + A_U32;                        \
        uint32_t h00 = pack2_f16(rb0.x, rb0.y), h01 = pack2_f16(rb0.z, rb0.w); \
        uint32_t h10 = pack2_f16(rb1.x, rb1.y), h11 = pack2_f16(rb1.z, rb1.w); \
        int r0 = (2*bp_p)     * (B_PITCH/4) + bp_nq * 2;                    \
        int r1 = (2*bp_p + 1) * (B_PITCH/4) + bp_nq * 2;                    \
        *(uint2*)&Bh[r0] = make_uint2(h00, h01);                            \
        *(uint2*)&Bh[r1] = make_uint2(h10, h11);                            \
    } while (0)

    // prologue
    ISSUE_A(0, ks);
    CP_COMMIT();
    if (NCH > 1) ISSUE_A(1, ks + 32);
    CP_COMMIT();
    LOAD_B(ks);
    STORE_B(0);
    if (NCH > 1) LOAD_B(ks + 32);
    CP_WAIT1();
    __syncthreads();

    for (int c = 0; c < NCH; c++) {
        const int buf = c & 1;
        const uint32_t AhA = sbase + (uint32_t)(buf * BUF_BYTES) + a_off;
        const uint32_t BhA = sbase + (uint32_t)(buf * BUF_BYTES + A_BYTES) + b_off;

        #pragma unroll
        for (int s = 0; s < 2; s++) {
            uint32_t a[2][4], bh[2][4];
            LDSM_X4(a[0], AhA + s * 32);
            LDSM_X4(a[1], AhA + s * 32 + 16 * A_PITCH);
            LDSM_X4T(bh[0], BhA + s * (16 * B_PITCH));
            LDSM_X4T(bh[1], BhA + s * (16 * B_PITCH) + 32);

            #pragma unroll
            for (int mt = 0; mt < 2; mt++) {
                #pragma unroll
                for (int ntp = 0; ntp < 2; ntp++) {
                    MMA_F16(acc[mt][2*ntp+0], a[mt], bh[ntp][0], bh[ntp][1]);
                    MMA_F16(acc[mt][2*ntp+1], a[mt], bh[ntp][2], bh[ntp][3]);
                }
            }
        }

        __syncthreads();                       // all warps done reading buf
        if (c + 2 < NCH) ISSUE_A(buf, ks + (c + 2) * 32);
        CP_COMMIT();
        if (c + 1 < NCH) STORE_B(buf ^ 1);     // regs for chunk c+1
        if (c + 2 < NCH) LOAD_B(ks + (c + 2) * 32);
        CP_WAIT1();                            // A(c+1) landed
        __syncthreads();                       // STS + cp.async visible
    }

    // epilogue: partial sums
    #pragma unroll
    for (int mt = 0; mt < 2; mt++) {
        int row = mbase + mt * 16 + gid;
        float* base = part + ((size_t)blockIdx.y * 128 + row) * HID_ + n0 + nbase;
        #pragma unroll
        for (int nt = 0; nt < 4; nt++) {
            float* d = base + nt * 8 + tig * 2;
            *(float2*)d               = make_float2(acc[mt][nt][0], acc[mt][nt][1]);
            *(float2*)(d + 8 * HID_)  = make_float2(acc[mt][nt][2], acc[mt][nt][3]);
        }
    }
    #undef ISSUE_A
    #undef LOAD_B
    #undef STORE_B
}

// ---------------------------------------------------------------------------
// Kernel 4a: split-K reduce + bias + relu -> f16 out (feeds next GEMM)
// ---------------------------------------------------------------------------
__global__ void reduce_bias_h_kernel(int S, const float* __restrict__ part,
                                     const float* __restrict__ bias,
                                     __half* __restrict__ out)
{
    int i4 = blockIdx.x * 256 + threadIdx.x;
    const int MN = B_ * HID_;
    int base = i4 * 4;
    if (base >= MN) return;
    float4 s = make_float4(0.f, 0.f, 0.f, 0.f);
    for (int p = 0; p < S; p++) {
        float4 v = *(const float4*)(part + (size_t)p * MN + base);
        s.x += v.x; s.y += v.y; s.z += v.z; s.w += v.w;
    }
    int n = base & (HID_ - 1);
    s.x = fmaxf(s.x + bias[n + 0], 0.f);
    s.y = fmaxf(s.y + bias[n + 1], 0.f);
    s.z = fmaxf(s.z + bias[n + 2], 0.f);
    s.w = fmaxf(s.w + bias[n + 3], 0.f);
    __half2 h0 = __floats2half2_rn(s.x, s.y);
    __half2 h1 = __floats2half2_rn(s.z, s.w);
    uint2 o;
    o.x = *(uint32_t*)&h0; o.y = *(uint32_t*)&h1;
    *(uint2*)(out + base) = o;
}

// ---------------------------------------------------------------------------
// Kernel 4b: split-K reduce + bias + relu -> f32 out (feeds fc3)
// ---------------------------------------------------------------------------
__global__ void reduce_bias_f_kernel(int S, const float* __restrict__ part,
                                     const float* __restrict__ bias,
                                     float* __restrict__ out)
{
    int i4 = blockIdx.x * 256 + threadIdx.x;
    const int MN = B_ * HID_;
    int base = i4 * 4;
    if (base >= MN) return;
    float4 s = make_float4(0.f, 0.f, 0.f, 0.f);
    for (int p = 0; p < S; p++) {
        float4 v = *(const float4*)(part + (size_t)p * MN + base);
        s.x += v.x; s.y += v.y; s.z += v.z; s.w += v.w;
    }
    int n = base & (HID_ - 1);
    s.x = fmaxf(s.x + bias[n + 0], 0.f);
    s.y = fmaxf(s.y + bias[n + 1], 0.f);
    s.z = fmaxf(s.z + bias[n + 2], 0.f);
    s.w = fmaxf(s.w + bias[n + 3], 0.f);
    *(float4*)(out + base) = s;
}

// ---------------------------------------------------------------------------
// Kernel 5a: transpose w3 [4096,19] -> w3t [19,4096]
// ---------------------------------------------------------------------------
__global__ void w3t_kernel(const float* __restrict__ w3, float* __restrict__ w3t)
{
    int k = blockIdx.x * 256 + threadIdx.x;
    if (k >= HID_) return;
    #pragma unroll
    for (int c = 0; c < FG_; c++)
        w3t[c * HID_ + k] = w3[k * FG_ + c];
}

// ---------------------------------------------------------------------------
// Kernel 5b: final FC  out[b,col] = dot(h2[b], w3t[col]) + b3[col]
// ---------------------------------------------------------------------------
__global__ void fc3_kernel(const float* __restrict__ A, const float* __restrict__ Wt,
                           const float* __restrict__ bias, float* __restrict__ out)
{
    int gw   = blockIdx.x * 8 + (threadIdx.x >> 5);
    int lane = threadIdx.x & 31;
    if (gw >= B_ * FG_) return;
    int b = gw / FG_, col = gw - b * FG_;

    const float4* a = (const float4*)(A  + (size_t)b   * HID_);
    const float4* w = (const float4*)(Wt + (size_t)col * HID_);
    float s = 0.f;
    #pragma unroll 4
    for (int i = lane; i < HID_/4; i += 32) {
        float4 av = a[i], wv = w[i];
        s += av.x*wv.x + av.y*wv.y + av.z*wv.z + av.w*wv.w;
    }
    #pragma unroll
    for (int o = 16; o; o >>= 1) s += __shfl_xor_sync(0xffffffffu, s, o);
    if (lane == 0) out[b * FG_ + col] = s + bias[col];
}

// ---------------------------------------------------------------------------
extern "C" void kernel_launch(void* const* d_in, const int* in_sizes, int n_in,
                              void* d_out, int out_size)
{
    const float* loc      = (const float*)d_in[0];
    const float* conf     = (const float*)d_in[1];
    const float* priors   = (const float*)d_in[2];
    const float* features = (const float*)d_in[3];
    const float* w1 = (const float*)d_in[4];
    const float* b1 = (const float*)d_in[5];
    const float* w2 = (const float*)d_in[6];
    const float* b2 = (const float*)d_in[7];
    const float* w3 = (const float*)d_in[8];
    const float* b3 = (const float*)d_in[9];
    float* out = (float*)d_out;

    void *pfH, *p1h, *p2, *ppart, *pw3t;
    cudaGetSymbolAddress(&pfH,   g_featH);
    cudaGetSymbolAddress(&p1h,   g_h1h);
    cudaGetSymbolAddress(&p2,    g_h2);
    cudaGetSymbolAddress(&ppart, g_part);
    cudaGetSymbolAddress(&pw3t,  g_w3t);

    best_prior_kernel<<<B_, 256>>>(loc, conf, priors, out);
    extract_kernel<<<dim3(B_, C_/8), 256>>>(features);
    w3t_kernel<<<HID_/256, 256>>>(w3, (float*)pw3t);

    // GEMM1: [128,512] @ [512,4096], split-K=4 (KSPLIT=128, NCH=4)
    gemm_hyb_kernel<<<dim3(HID_/64, 4), 256, 2*BUF_BYTES>>>(C_, 128,
        (const __half*)pfH, w1, (float*)ppart);
    reduce_bias_h_kernel<<<(B_*HID_/4 + 255)/256, 256>>>(4,
        (const float*)ppart, b1, (__half*)p1h);

    // GEMM2: [128,4096] @ [4096,4096], split-K=4 (KSPLIT=1024, NCH=32)
    gemm_hyb_kernel<<<dim3(HID_/64, 4), 256, 2*BUF_BYTES>>>(HID_, 1024,
        (const __half*)p1h, w2, (float*)ppart);
    reduce_bias_f_kernel<<<(B_*HID_/4 + 255)/256, 256>>>(4,
        (const float*)ppart, b2, (float*)p2);

    fc3_kernel<<<(B_*FG_ + 7)/8, 256>>>((const float*)p2, (const float*)pw3t, b3, out);
}

// round 12
// speedup vs baseline: 1.4558x; 1.0855x over previous
#include <cuda_runtime.h>
#include <cuda_fp16.h>
#include <math.h>
#include <cfloat>
#include <cstdint>

#define B_   128
#define N_   8732
#define C_   512
#define H_   19
#define FG_  19
#define HID_ 4096

// ---------------------------------------------------------------------------
// scratch (device globals — no allocation allowed)
// ---------------------------------------------------------------------------
__device__ __align__(16) __half g_featH[B_*C_];
__device__ __align__(16) __half g_h1h[B_*HID_];
__device__ float g_h2[B_*HID_];
__device__ int   g_bins[B_*4];
__device__ int   g_valid[B_];
__device__ float g_part[4*B_*HID_];     // split-K partials (S<=4)
__device__ float g_w3t[FG_*HID_];       // w3 transposed

// ---------------------------------------------------------------------------
// helpers
// ---------------------------------------------------------------------------
#define MMA_F16(c, a, b0, b1)                                               \
    asm volatile("mma.sync.aligned.m16n8k16.row.col.f32.f16.f16.f32 "       \
        "{%0,%1,%2,%3}, {%4,%5,%6,%7}, {%8,%9}, {%0,%1,%2,%3};"             \
        : "+f"((c)[0]), "+f"((c)[1]), "+f"((c)[2]), "+f"((c)[3])            \
        : "r"((a)[0]), "r"((a)[1]), "r"((a)[2]), "r"((a)[3]),               \
          "r"(b0), "r"(b1))

#define LDSM_X4(r, addr)                                                    \
    asm volatile("ldmatrix.sync.aligned.m8n8.x4.shared.b16 "                \
        "{%0,%1,%2,%3}, [%4];"                                              \
        : "=r"((r)[0]), "=r"((r)[1]), "=r"((r)[2]), "=r"((r)[3])            \
        : "r"(addr) : "memory")

#define LDSM_X4T(r, addr)                                                   \
    asm volatile("ldmatrix.sync.aligned.m8n8.x4.trans.shared.b16 "          \
        "{%0,%1,%2,%3}, [%4];"                                              \
        : "=r"((r)[0]), "=r"((r)[1]), "=r"((r)[2]), "=r"((r)[3])            \
        : "r"(addr) : "memory")

#define CP_ASYNC16(dst, src)                                                \
    asm volatile("cp.async.cg.shared.global [%0], [%1], 16;"                \
        :: "r"(dst), "l"(src) : "memory")
#define CP_COMMIT()  asm volatile("cp.async.commit_group;" ::: "memory")
#define CP_WAIT1()   asm volatile("cp.async.wait_group 1;" ::: "memory")

__device__ __forceinline__ uint32_t pack2_f16(float x0, float x1)
{
    __half2 h = __floats2half2_rn(x0, x1);
    return *(uint32_t*)&h;
}

// ---------------------------------------------------------------------------
// Kernel 1: per-batch best car prior (float4-vectorized conf reads)
// ---------------------------------------------------------------------------
__global__ void best_prior_kernel(const float* __restrict__ loc,
                                  const float* __restrict__ conf,
                                  const float* __restrict__ priors,
                                  float* __restrict__ out)
{
    int b = blockIdx.x, tid = threadIdx.x;
    const float4* cb4 = (const float4*)(conf + (size_t)b * N_ * 2);
    const int NJ = N_ / 2;                 // 4366 float4s, N_ even

    float best = -FLT_MAX;
    int   bidx = 0x7fffffff;
    int   anyc = 0;

    for (int j = tid; j < NJ; j += 256) {
        float4 c4 = cb4[j];
        int i0 = 2 * j, i1 = 2 * j + 1;
        if (c4.y > c4.x) {
            anyc = 1;
            float p1 = 1.0f / (1.0f + expf(c4.x - c4.y));
            if (p1 > best || (p1 == best && i0 < bidx)) { best = p1; bidx = i0; }
        }
        if (c4.w > c4.z) {
            anyc = 1;
            float p1 = 1.0f / (1.0f + expf(c4.z - c4.w));
            if (p1 > best || (p1 == best && i1 < bidx)) { best = p1; bidx = i1; }
        }
    }

    int has = __syncthreads_or(anyc);

    __shared__ float sv[256];
    __shared__ int   si[256];
    sv[tid] = best; si[tid] = bidx;
    __syncthreads();
    for (int s = 128; s > 0; s >>= 1) {
        if (tid < s) {
            float v2 = sv[tid+s]; int i2 = si[tid+s];
            if (v2 > sv[tid] || (v2 == sv[tid] && i2 < si[tid])) { sv[tid]=v2; si[tid]=i2; }
        }
        __syncthreads();
    }

    if (tid == 0) {
        float bx0=0.f,bx1=0.f,bx2=0.f,bx3=0.f;
        int v = 0;
        int n0=0,n1=0,n2=0,n3=0;
        if (has) {
            int idx = si[0];
            float p0 = priors[4*idx+0], p1p = priors[4*idx+1];
            float p2 = priors[4*idx+2], p3  = priors[4*idx+3];
            const float* l = loc + ((size_t)b * N_ + idx) * 4;
            float cx = p0 + l[0] * 0.1f * p2;
            float cy = p1p + l[1] * 0.1f * p3;
            float w  = p2 * expf(l[2] * 0.2f);
            float h  = p3 * expf(l[3] * 0.2f);
            float x1 = cx - 0.5f*w, y1 = cy - 0.5f*h;
            float x2 = x1 + w,      y2 = y1 + h;
            v = (x2 > x1) && (y2 > y1);
            bx0 = fminf(fmaxf(x1, 0.f), 1.f);
            bx1 = fminf(fmaxf(y1, 0.f), 1.f);
            bx2 = fminf(fmaxf(x2, 0.f), 1.f);
            bx3 = fminf(fmaxf(y2, 0.f), 1.f);
            const float step = (float)(300.0 / 19.0);
            float t;
            t = fminf(fmaxf(bx0*300.0f,0.f),300.f)/step; n0 = (int)floorf(fminf(fmaxf(t,0.f),18.f));
            t = fminf(fmaxf(bx1*300.0f,0.f),300.f)/step; n1 = (int)floorf(fminf(fmaxf(t,0.f),18.f));
            t = fminf(fmaxf(bx2*300.0f,0.f),300.f)/step; n2 = (int)floorf(fminf(fmaxf(t,0.f),18.f));
            t = fminf(fmaxf(bx3*300.0f,0.f),300.f)/step; n3 = (int)floorf(fminf(fmaxf(t,0.f),18.f));
        }
        out[2432 + b*4 + 0] = bx0;
        out[2432 + b*4 + 1] = bx1;
        out[2432 + b*4 + 2] = bx2;
        out[2432 + b*4 + 3] = bx3;
        out[2944 + b] = v ? 1.0f : 0.0f;
        g_valid[b]   = v;
        g_bins[b*4+0] = n0; g_bins[b*4+1] = n1;
        g_bins[b*4+2] = n2; g_bins[b*4+3] = n3;
    }
}

// ---------------------------------------------------------------------------
// Kernel 2: masked global max pool -> g_featH [B, C] f16
// one warp = 4 channels; all 48 loads issued before any max logic (high MLP)
// ---------------------------------------------------------------------------
__global__ void extract_kernel(const float* __restrict__ feats)
{
    int b     = blockIdx.x;
    int warp  = threadIdx.x >> 5;
    int lane  = threadIdx.x & 31;
    int cbase = blockIdx.y * 32 + warp * 4;

    if (!g_valid[b]) {
        if (lane < 4) g_featH[b*C_ + cbase + lane] = __float2half(0.f);
        return;
    }

    int x1 = g_bins[b*4+0], y1 = g_bins[b*4+1];
    int x2 = g_bins[b*4+2], y2 = g_bins[b*4+3];

    const float* f0 = feats + ((size_t)(b * C_ + cbase)) * (H_ * H_);

    // issue all loads first: 4 channels x 12 loads
    float v[4][12];
    #pragma unroll
    for (int ch = 0; ch < 4; ch++) {
        const float* f = f0 + ch * (H_ * H_);
        #pragma unroll
        for (int i = 0; i < 11; i++) v[ch][i] = f[lane + 32 * i];
        v[ch][11] = (lane < 9) ? f[352 + lane] : -FLT_MAX;
    }

    // precompute lane masks (shared across channels)
    bool inm[12];
    #pragma unroll
    for (int i = 0; i < 11; i++) {
        int t = lane + 32 * i;
        int y = t / H_;
        int x = t - y * H_;
        inm[i] = (y >= y1) & (y <= y2) & (x >= x1) & (x <= x2);
    }
    {
        int t = 352 + lane;
        int y = t / H_;
        int x = t - y * H_;
        inm[11] = (lane < 9) & (y >= y1) & (y <= y2) & (x >= x1) & (x <= x2);
    }

    #pragma unroll
    for (int ch = 0; ch < 4; ch++) {
        float m = -FLT_MAX;
        #pragma unroll
        for (int i = 0; i < 12; i++)
            m = fmaxf(m, inm[i] ? v[ch][i] : -FLT_MAX);
        #pragma unroll
        for (int o = 16; o; o >>= 1) m = fmaxf(m, __shfl_xor_sync(0xffffffffu, m, o));
        if (lane == 0) g_featH[b*C_ + cbase + ch] = __float2half_rn(m);
    }
}

// ---------------------------------------------------------------------------
// Kernel 3: hybrid GEMM — A f16 via cp.async, B f32 fused-convert in stager.
//   part[split][128][HID_] = A[128, Ktot](f16) @ Bw[Ktot, HID_](f32)
//   BM=128, BN=64, BK=32; 8 warps, warp tile 32x32; double-buffered.
// ---------------------------------------------------------------------------
#define A_PITCH   80               // bytes per A row (64 data + 16 pad)
#define B_PITCH   144              // bytes per B k-row (128 data + 16 pad)
#define A_BYTES   (128*A_PITCH)    // 10240
#define B_BYTES   (32*B_PITCH)     //  4608
#define BUF_BYTES (A_BYTES + B_BYTES)   // 14848
#define BUF_U32   (BUF_BYTES/4)
#define A_U32     (A_BYTES/4)

__global__ __launch_bounds__(256, 2)
void gemm_hyb_kernel(int Ktot, int KSPLIT,
                     const __half* __restrict__ Aw, const float* __restrict__ Bw,
                     float* __restrict__ part)
{
    extern __shared__ uint32_t sm[];

    const int tid  = threadIdx.x;
    const int wid  = tid >> 5;
    const int lane = tid & 31;
    const int gid  = lane >> 2;
    const int tig  = lane & 3;
    const int n0   = blockIdx.x * 64;
    const int ks   = blockIdx.y * KSPLIT;
    const int NCH  = KSPLIT >> 5;
    const int mbase = (wid & 3) * 32;
    const int nbase = (wid >> 2) * 32;

    const int bp_p  = tid >> 4;      // 0..15
    const int bp_nq = tid & 15;      // 0..15

    const uint32_t sbase = (uint32_t)__cvta_generic_to_shared(sm);

    const int l15  = lane & 15;
    const int lhi8 = (lane >> 4) * 8;
    const uint32_t a_off = (uint32_t)((mbase + l15) * A_PITCH + lhi8 * 2);
    const uint32_t b_off = (uint32_t)(l15 * B_PITCH + (nbase + lhi8) * 2);

    float acc[2][4][4];
    #pragma unroll
    for (int i = 0; i < 2; i++)
        #pragma unroll
        for (int j = 0; j < 4; j++)
            #pragma unroll
            for (int q = 0; q < 4; q++) acc[i][j][q] = 0.f;

    float4 rb0, rb1;

    #define ISSUE_A(buf, k0) do {                                           \
        uint32_t dA = sbase + (uint32_t)((buf) * BUF_BYTES);                \
        _Pragma("unroll")                                                   \
        for (int j = 0; j < 2; j++) {                                       \
            int idx = tid + j * 256;                                        \
            int row = idx >> 2, q = idx & 3;                                \
            const __half* src = Aw + (size_t)row * Ktot + (k0) + q * 8;     \
            CP_ASYNC16(dA + (uint32_t)(row * A_PITCH + q * 16), src);       \
        }                                                                   \
    } while (0)

    #define LOAD_B(k0) do {                                                 \
        const float* bp = Bw + (size_t)((k0) + 2 * bp_p) * HID_             \
                          + n0 + bp_nq * 4;                                 \
        rb0 = *(const float4*)bp;                                           \
        rb1 = *(const float4*)(bp + HID_);                                  \
    } while (0)

    #define STORE_B(buf) do {                                               \
        uint32_t* Bh = sm + (buf) * BUF_U32 + A_U32;                        \
        uint32_t h00 = pack2_f16(rb0.x, rb0.y), h01 = pack2_f16(rb0.z, rb0.w); \
        uint32_t h10 = pack2_f16(rb1.x, rb1.y), h11 = pack2_f16(rb1.z, rb1.w); \
        int r0 = (2*bp_p)     * (B_PITCH/4) + bp_nq * 2;                    \
        int r1 = (2*bp_p + 1) * (B_PITCH/4) + bp_nq * 2;                    \
        *(uint2*)&Bh[r0] = make_uint2(h00, h01);                            \
        *(uint2*)&Bh[r1] = make_uint2(h10, h11);                            \
    } while (0)

    // prologue
    ISSUE_A(0, ks);
    CP_COMMIT();
    if (NCH > 1) ISSUE_A(1, ks + 32);
    CP_COMMIT();
    LOAD_B(ks);
    STORE_B(0);
    if (NCH > 1) LOAD_B(ks + 32);
    CP_WAIT1();
    __syncthreads();

    for (int c = 0; c < NCH; c++) {
        const int buf = c & 1;
        const uint32_t AhA = sbase + (uint32_t)(buf * BUF_BYTES) + a_off;
        const uint32_t BhA = sbase + (uint32_t)(buf * BUF_BYTES + A_BYTES) + b_off;

        #pragma unroll
        for (int s = 0; s < 2; s++) {
            uint32_t a[2][4], bh[2][4];
            LDSM_X4(a[0], AhA + s * 32);
            LDSM_X4(a[1], AhA + s * 32 + 16 * A_PITCH);
            LDSM_X4T(bh[0], BhA + s * (16 * B_PITCH));
            LDSM_X4T(bh[1], BhA + s * (16 * B_PITCH) + 32);

            #pragma unroll
            for (int mt = 0; mt < 2; mt++) {
                #pragma unroll
                for (int ntp = 0; ntp < 2; ntp++) {
                    MMA_F16(acc[mt][2*ntp+0], a[mt], bh[ntp][0], bh[ntp][1]);
                    MMA_F16(acc[mt][2*ntp+1], a[mt], bh[ntp][2], bh[ntp][3]);
                }
            }
        }

        __syncthreads();
        if (c + 2 < NCH) ISSUE_A(buf, ks + (c + 2) * 32);
        CP_COMMIT();
        if (c + 1 < NCH) STORE_B(buf ^ 1);
        if (c + 2 < NCH) LOAD_B(ks + (c + 2) * 32);
        CP_WAIT1();
        __syncthreads();
    }

    // epilogue: partial sums
    #pragma unroll
    for (int mt = 0; mt < 2; mt++) {
        int row = mbase + mt * 16 + gid;
        float* base = part + ((size_t)blockIdx.y * 128 + row) * HID_ + n0 + nbase;
        #pragma unroll
        for (int nt = 0; nt < 4; nt++) {
            float* d = base + nt * 8 + tig * 2;
            *(float2*)d               = make_float2(acc[mt][nt][0], acc[mt][nt][1]);
            *(float2*)(d + 8 * HID_)  = make_float2(acc[mt][nt][2], acc[mt][nt][3]);
        }
    }
    #undef ISSUE_A
    #undef LOAD_B
    #undef STORE_B
}

// ---------------------------------------------------------------------------
// Kernel 4a: split-K reduce + bias + relu -> f16 out (feeds next GEMM)
// ---------------------------------------------------------------------------
__global__ void reduce_bias_h_kernel(int S, const float* __restrict__ part,
                                     const float* __restrict__ bias,
                                     __half* __restrict__ out)
{
    int i4 = blockIdx.x * 256 + threadIdx.x;
    const int MN = B_ * HID_;
    int base = i4 * 4;
    if (base >= MN) return;
    float4 s = make_float4(0.f, 0.f, 0.f, 0.f);
    for (int p = 0; p < S; p++) {
        float4 v = *(const float4*)(part + (size_t)p * MN + base);
        s.x += v.x; s.y += v.y; s.z += v.z; s.w += v.w;
    }
    int n = base & (HID_ - 1);
    s.x = fmaxf(s.x + bias[n + 0], 0.f);
    s.y = fmaxf(s.y + bias[n + 1], 0.f);
    s.z = fmaxf(s.z + bias[n + 2], 0.f);
    s.w = fmaxf(s.w + bias[n + 3], 0.f);
    __half2 h0 = __floats2half2_rn(s.x, s.y);
    __half2 h1 = __floats2half2_rn(s.z, s.w);
    uint2 o;
    o.x = *(uint32_t*)&h0; o.y = *(uint32_t*)&h1;
    *(uint2*)(out + base) = o;
}

// ---------------------------------------------------------------------------
// Kernel 4b: split-K reduce + bias + relu -> f32 out (feeds fc3)
// ---------------------------------------------------------------------------
__global__ void reduce_bias_f_kernel(int S, const float* __restrict__ part,
                                     const float* __restrict__ bias,
                                     float* __restrict__ out)
{
    int i4 = blockIdx.x * 256 + threadIdx.x;
    const int MN = B_ * HID_;
    int base = i4 * 4;
    if (base >= MN) return;
    float4 s = make_float4(0.f, 0.f, 0.f, 0.f);
    for (int p = 0; p < S; p++) {
        float4 v = *(const float4*)(part + (size_t)p * MN + base);
        s.x += v.x; s.y += v.y; s.z += v.z; s.w += v.w;
    }
    int n = base & (HID_ - 1);
    s.x = fmaxf(s.x + bias[n + 0], 0.f);
    s.y = fmaxf(s.y + bias[n + 1], 0.f);
    s.z = fmaxf(s.z + bias[n + 2], 0.f);
    s.w = fmaxf(s.w + bias[n + 3], 0.f);
    *(float4*)(out + base) = s;
}

// ---------------------------------------------------------------------------
// Kernel 5a: transpose w3 [4096,19] -> w3t [19,4096]
// ---------------------------------------------------------------------------
__global__ void w3t_kernel(const float* __restrict__ w3, float* __restrict__ w3t)
{
    int k = blockIdx.x * 256 + threadIdx.x;
    if (k >= HID_) return;
    #pragma unroll
    for (int c = 0; c < FG_; c++)
        w3t[c * HID_ + k] = w3[k * FG_ + c];
}

// ---------------------------------------------------------------------------
// Kernel 5b: final FC  out[b,col] = dot(h2[b], w3t[col]) + b3[col]
// ---------------------------------------------------------------------------
__global__ void fc3_kernel(const float* __restrict__ A, const float* __restrict__ Wt,
                           const float* __restrict__ bias, float* __restrict__ out)
{
    int gw   = blockIdx.x * 8 + (threadIdx.x >> 5);
    int lane = threadIdx.x & 31;
    if (gw >= B_ * FG_) return;
    int b = gw / FG_, col = gw - b * FG_;

    const float4* a = (const float4*)(A  + (size_t)b   * HID_);
    const float4* w = (const float4*)(Wt + (size_t)col * HID_);
    float s = 0.f;
    #pragma unroll 4
    for (int i = lane; i < HID_/4; i += 32) {
        float4 av = a[i], wv = w[i];
        s += av.x*wv.x + av.y*wv.y + av.z*wv.z + av.w*wv.w;
    }
    #pragma unroll
    for (int o = 16; o; o >>= 1) s += __shfl_xor_sync(0xffffffffu, s, o);
    if (lane == 0) out[b * FG_ + col] = s + bias[col];
}

// ---------------------------------------------------------------------------
extern "C" void kernel_launch(void* const* d_in, const int* in_sizes, int n_in,
                              void* d_out, int out_size)
{
    const float* loc      = (const float*)d_in[0];
    const float* conf     = (const float*)d_in[1];
    const float* priors   = (const float*)d_in[2];
    const float* features = (const float*)d_in[3];
    const float* w1 = (const float*)d_in[4];
    const float* b1 = (const float*)d_in[5];
    const float* w2 = (const float*)d_in[6];
    const float* b2 = (const float*)d_in[7];
    const float* w3 = (const float*)d_in[8];
    const float* b3 = (const float*)d_in[9];
    float* out = (float*)d_out;

    void *pfH, *p1h, *p2, *ppart, *pw3t;
    cudaGetSymbolAddress(&pfH,   g_featH);
    cudaGetSymbolAddress(&p1h,   g_h1h);
    cudaGetSymbolAddress(&p2,    g_h2);
    cudaGetSymbolAddress(&ppart, g_part);
    cudaGetSymbolAddress(&pw3t,  g_w3t);

    best_prior_kernel<<<B_, 256>>>(loc, conf, priors, out);
    extract_kernel<<<dim3(B_, C_/32), 256>>>(features);
    w3t_kernel<<<HID_/256, 256>>>(w3, (float*)pw3t);

    // GEMM1: [128,512] @ [512,4096], split-K=4 (KSPLIT=128, NCH=4)
    gemm_hyb_kernel<<<dim3(HID_/64, 4), 256, 2*BUF_BYTES>>>(C_, 128,
        (const __half*)pfH, w1, (float*)ppart);
    reduce_bias_h_kernel<<<(B_*HID_/4 + 255)/256, 256>>>(4,
        (const float*)ppart, b1, (__half*)p1h);

    // GEMM2: [128,4096] @ [4096,4096], split-K=4 (KSPLIT=1024, NCH=32)
    gemm_hyb_kernel<<<dim3(HID_/64, 4), 256, 2*BUF_BYTES>>>(HID_, 1024,
        (const __half*)p1h, w2, (float*)ppart);
    reduce_bias_f_kernel<<<(B_*HID_/4 + 255)/256, 256>>>(4,
        (const float*)ppart, b2, (float*)p2);

    fc3_kernel<<<(B_*FG_ + 7)/8, 256>>>((const float*)p2, (const float*)pw3t, b3, out);
}